// round 9
// baseline (speedup 1.0000x reference)
#include <cuda_runtime.h>

// L0 contraction: out[b,n] = cg_n * sum_{m in deg-block n} sphc[b,m]^2
// Row of 15 floats: [0:3) deg1, [3:8) deg2, [8:15) deg3.
// Traffic floor: 240MB read + 48MB write = 288MB (~36us @ 8TB/s spec).
// R6: 192-row tiles — the max smem that keeps 16 blocks/SM (64 warps,
//     100% occ) incl. ~1KB/block driver reserve; +20% bytes per barrier
//     vs R4. Streaming cache hints on both one-pass streams.

constexpr int THREADS = 128;
constexpr int ROWS_PER_BLOCK = 192;
constexpr int M = 15;
constexpr int NV = ROWS_PER_BLOCK * M / 4;   // 720 float4 in
constexpr int NO = ROWS_PER_BLOCK * 3 / 4;   // 144 float4 out

__global__ __launch_bounds__(THREADS, 16) void l0_contraction_kernel(
    const float* __restrict__ sphc,
    const float* __restrict__ cg,
    float* __restrict__ out,
    int B)
{
    __shared__ float s_in[ROWS_PER_BLOCK * M];   // 11520 B
    __shared__ float s_out[ROWS_PER_BLOCK * 3];  //  2304 B

    const float c0 = __ldg(cg + 0);  // 1/sqrt(3)
    const float c1 = __ldg(cg + 3);  // 1/sqrt(5)
    const float c2 = __ldg(cg + 8);  // 1/sqrt(7)

    const long long row0 = (long long)blockIdx.x * ROWS_PER_BLOCK;
    const int tid = threadIdx.x;
    const int nrows = (int)min((long long)ROWS_PER_BLOCK, (long long)B - row0);

    if (nrows == ROWS_PER_BLOCK) {
        // ---- full tile ----
        // 192 rows * 60B = 11520B per tile; tile base 16B-aligned (11520%16==0).
        const float4* gin = reinterpret_cast<const float4*>(sphc + row0 * M);
        float4* s4 = reinterpret_cast<float4*>(s_in);
        #pragma unroll
        for (int i = 0; i < (NV + THREADS - 1) / THREADS; i++) {  // 6 iters
            const int idx = tid + i * THREADS;
            if (idx < NV) s4[idx] = __ldcs(gin + idx);  // evict-first stream
        }
        __syncthreads();

        // 192 rows over 128 threads: iter0 all lanes, iter1 lanes < 64.
        #pragma unroll
        for (int j = 0; j < 2; j++) {
            const int r = tid + j * THREADS;
            if (r < ROWS_PER_BLOCK) {
                const float* x = s_in + r * M;   // stride 15: conflict-free
                float a = x[0]*x[0] + x[1]*x[1] + x[2]*x[2];
                float b = x[3]*x[3] + x[4]*x[4] + x[5]*x[5] + x[6]*x[6] + x[7]*x[7];
                float c = x[8]*x[8] + x[9]*x[9] + x[10]*x[10] + x[11]*x[11]
                        + x[12]*x[12] + x[13]*x[13] + x[14]*x[14];
                s_out[r * 3 + 0] = a * c0;
                s_out[r * 3 + 1] = b * c1;
                s_out[r * 3 + 2] = c * c2;
            }
        }
        __syncthreads();

        float4* gout = reinterpret_cast<float4*>(out + row0 * 3);
        const float4* so4 = reinterpret_cast<const float4*>(s_out);
        #pragma unroll
        for (int i = 0; i < (NO + THREADS - 1) / THREADS; i++) {  // 2 iters
            const int idx = tid + i * THREADS;
            if (idx < NO) __stcs(gout + idx, so4[idx]);
        }
    } else {
        // ---- tail tile: scalar, guarded ----
        const float* gin = sphc + row0 * M;
        const int nf = nrows * M;
        for (int i = tid; i < nf; i += THREADS) s_in[i] = gin[i];
        __syncthreads();

        for (int r = tid; r < nrows; r += THREADS) {
            const float* x = s_in + r * M;
            float a = x[0]*x[0] + x[1]*x[1] + x[2]*x[2];
            float b = x[3]*x[3] + x[4]*x[4] + x[5]*x[5] + x[6]*x[6] + x[7]*x[7];
            float c = x[8]*x[8] + x[9]*x[9] + x[10]*x[10] + x[11]*x[11]
                    + x[12]*x[12] + x[13]*x[13] + x[14]*x[14];
            s_out[r * 3 + 0] = a * c0;
            s_out[r * 3 + 1] = b * c1;
            s_out[r * 3 + 2] = c * c2;
        }
        __syncthreads();

        float* gout = out + row0 * 3;
        const int no = nrows * 3;
        for (int i = tid; i < no; i += THREADS) gout[i] = s_out[i];
    }
}

extern "C" void kernel_launch(void* const* d_in, const int* in_sizes, int n_in,
                              void* d_out, int out_size) {
    const float* sphc = (const float*)d_in[0];
    const float* cg   = (const float*)d_in[1];
    // d_in[2] = segment_ids (structure is compile-time: 3/5/7 blocks)
    float* out = (float*)d_out;

    const int B = in_sizes[0] / M;  // 4,000,000
    const int grid = (B + ROWS_PER_BLOCK - 1) / ROWS_PER_BLOCK;  // 20834
    l0_contraction_kernel<<<grid, THREADS>>>(sphc, cg, out, B);
}

// round 10
// speedup vs baseline: 1.2845x; 1.2845x over previous
#include <cuda_runtime.h>

// L0 contraction: out[b,n] = cg_n * sum_{m in deg-block n} sphc[b,m]^2
// Row of 15 floats: [0:3) deg1, [3:8) deg2, [8:15) deg3.
// Traffic floor: 240MB read + 48MB write = 288MB (~36us @ 8TB/s spec).
// R10: revert to proven R4 geometry (160-row tiles, 9.6KB smem, 16 blk/SM
//      = 64 warps) + drop output staging: direct per-row __stcs stores
//      (warp writes 384B contiguous -> all sectors full), one barrier/tile.

constexpr int THREADS = 128;
constexpr int ROWS_PER_BLOCK = 160;
constexpr int M = 15;
constexpr int NV = ROWS_PER_BLOCK * M / 4;   // 600 float4 in

__global__ __launch_bounds__(THREADS, 16) void l0_contraction_kernel(
    const float* __restrict__ sphc,
    const float* __restrict__ cg,
    float* __restrict__ out,
    int B)
{
    __shared__ float s_in[ROWS_PER_BLOCK * M];   // 9600 B

    const float c0 = __ldg(cg + 0);  // 1/sqrt(3)
    const float c1 = __ldg(cg + 3);  // 1/sqrt(5)
    const float c2 = __ldg(cg + 8);  // 1/sqrt(7)

    const long long row0 = (long long)blockIdx.x * ROWS_PER_BLOCK;
    const int tid = threadIdx.x;
    const int nrows = (int)min((long long)ROWS_PER_BLOCK, (long long)B - row0);

    if (nrows == ROWS_PER_BLOCK) {
        // ---- full tile ----
        // 160 rows * 60B = 9600B per tile; tile base 16B-aligned (9600%16==0).
        const float4* gin = reinterpret_cast<const float4*>(sphc + row0 * M);
        float4* s4 = reinterpret_cast<float4*>(s_in);
        #pragma unroll
        for (int i = 0; i < (NV + THREADS - 1) / THREADS; i++) {  // 5 iters
            const int idx = tid + i * THREADS;
            if (idx < NV) s4[idx] = __ldcs(gin + idx);  // evict-first stream
        }
        __syncthreads();

        // 160 rows over 128 threads: iter0 all lanes, iter1 lanes < 32.
        // Direct stores: each thread writes 3 consecutive floats; a warp
        // covers 384 contiguous bytes -> fully-utilized sectors.
        #pragma unroll
        for (int j = 0; j < 2; j++) {
            const int r = tid + j * THREADS;
            if (r < ROWS_PER_BLOCK) {
                const float* x = s_in + r * M;   // stride 15: conflict-free
                float a = x[0]*x[0] + x[1]*x[1] + x[2]*x[2];
                float b = x[3]*x[3] + x[4]*x[4] + x[5]*x[5] + x[6]*x[6] + x[7]*x[7];
                float c = x[8]*x[8] + x[9]*x[9] + x[10]*x[10] + x[11]*x[11]
                        + x[12]*x[12] + x[13]*x[13] + x[14]*x[14];
                float* o = out + (row0 + r) * 3;
                __stcs(o + 0, a * c0);
                __stcs(o + 1, b * c1);
                __stcs(o + 2, c * c2);
            }
        }
    } else {
        // ---- tail tile: scalar, guarded ----
        const float* gin = sphc + row0 * M;
        const int nf = nrows * M;
        for (int i = tid; i < nf; i += THREADS) s_in[i] = gin[i];
        __syncthreads();

        for (int r = tid; r < nrows; r += THREADS) {
            const float* x = s_in + r * M;
            float a = x[0]*x[0] + x[1]*x[1] + x[2]*x[2];
            float b = x[3]*x[3] + x[4]*x[4] + x[5]*x[5] + x[6]*x[6] + x[7]*x[7];
            float c = x[8]*x[8] + x[9]*x[9] + x[10]*x[10] + x[11]*x[11]
                    + x[12]*x[12] + x[13]*x[13] + x[14]*x[14];
            float* o = out + (row0 + r) * 3;
            o[0] = a * c0;
            o[1] = b * c1;
            o[2] = c * c2;
        }
    }
}

extern "C" void kernel_launch(void* const* d_in, const int* in_sizes, int n_in,
                              void* d_out, int out_size) {
    const float* sphc = (const float*)d_in[0];
    const float* cg   = (const float*)d_in[1];
    // d_in[2] = segment_ids (structure is compile-time: 3/5/7 blocks)
    float* out = (float*)d_out;

    const int B = in_sizes[0] / M;  // 4,000,000
    const int grid = (B + ROWS_PER_BLOCK - 1) / ROWS_PER_BLOCK;  // 25000
    l0_contraction_kernel<<<grid, THREADS>>>(sphc, cg, out, B);
}